// round 1
// baseline (speedup 1.0000x reference)
#include <cuda_runtime.h>
#include <math_constants.h>
#include <cstdint>

#define LSEQ 2048
#define BATCH 8
#define NROWS (BATCH*LSEQ)
#define K2N 32
#define K1N 16
#define NG 32
#define HIN 20
#define DM 128
#define DH 32
#define KDIM 640   // NG*HIN

// ---------------- device scratch (static, no allocation) ----------------
__device__ int   g_idx2[NROWS*K2N];
__device__ float g_M[(size_t)NROWS*KDIM];
__device__ float g_satt[NROWS];
__device__ float g_catt[NROWS];
__device__ float g_beta[NROWS];
__device__ float g_nodef[NROWS*2];

// ---------------- kernel 1: 32-NN per row (ascending d2, slot0 = self) ----
__global__ void __launch_bounds__(128) knn_kernel(const float* __restrict__ frame)
{
    __shared__ float d2s[4][LSEQ];
    int warp = threadIdx.x >> 5, lane = threadIdx.x & 31;
    int row  = blockIdx.x * 4 + warp;
    int b = row >> 11, l = row & (LSEQ-1);
    const float* fb = frame + (size_t)b * LSEQ * 12;

    float cx = fb[l*12+0], cy = fb[l*12+1], cz = fb[l*12+2];
    float sqi = cx*cx + cy*cy + cz*cz;

    float minv = CUDART_INF_F; int minp = LSEQ;
    float* dw = d2s[warp];
    #pragma unroll 4
    for (int t = 0; t < LSEQ/32; t++) {
        int m = lane + (t << 5);
        float mx = fb[m*12+0], my = fb[m*12+1], mz = fb[m*12+2];
        float sqm = mx*mx + my*my + mz*mz;
        float dot = cx*mx + cy*my + cz*mz;
        float d2 = (sqi + sqm) - 2.0f * dot;
        dw[m] = d2;
        if (d2 < minv || (d2 == minv && m < minp)) { minv = d2; minp = m; }
    }
    __syncwarp();

    int myidx = 0;
    for (int s = 0; s < K2N; s++) {
        float v = minv; int p = minp;
        #pragma unroll
        for (int off = 16; off > 0; off >>= 1) {
            float ov = __shfl_down_sync(0xffffffffu, v, off);
            int   op = __shfl_down_sync(0xffffffffu, p, off);
            if (ov < v || (ov == v && op < p)) { v = ov; p = op; }
        }
        p = __shfl_sync(0xffffffffu, p, 0);
        if (lane == s) myidx = p;
        if (minp == p) {                 // exactly one lane owns p (p%32)
            dw[p] = CUDART_INF_F;
            minv = CUDART_INF_F; minp = LSEQ;
            for (int t = 0; t < LSEQ/32; t++) {
                int m = lane + (t << 5);
                float d = dw[m];
                if (d < minv || (d == minv && m < minp)) { minv = d; minp = m; }
            }
        }
        __syncwarp();
    }
    g_idx2[row*K2N + lane] = myidx;   // coalesced, ascending d2
}

// ---------------- kernel 2: coords1 + gaussians1 + outer product M ----------
__global__ void __launch_bounds__(256) stage1_kernel(
    const float* __restrict__ frame, const float* __restrict__ attr,
    const int* __restrict__ seq,
    const float* __restrict__ gk1_centers, const float* __restrict__ gk1_prec)
{
    __shared__ float attr_s[8][K1N][HIN];
    __shared__ float co_s[8][K1N][7];
    int warp = threadIdx.x >> 5, lane = threadIdx.x & 31;
    int row  = blockIdx.x * 8 + warp;
    int b = row >> 11, l = row & (LSEQ-1);
    const float* fb = frame + (size_t)b * LSEQ * 12;

    if (lane < K1N) {
        int k = lane;
        int j = g_idx2[row*K2N + k];
        float fi[12];
        #pragma unroll
        for (int d = 0; d < 12; d++) fi[d] = fb[l*12+d];
        float cjx = fb[j*12+0], cjy = fb[j*12+1], cjz = fb[j*12+2];
        float zjx = fb[j*12+9], zjy = fb[j*12+10], zjz = fb[j*12+11];
        float dx = cjx - fi[0], dy = cjy - fi[1], dz = cjz - fi[2];
        float dist = sqrtf(dx*dx + dy*dy + dz*dz + 1e-12f);
        float e0 = dx*fi[3] + dy*fi[4] + dz*fi[5];
        float e1 = dx*fi[6] + dy*fi[7] + dz*fi[8];
        float e2 = dx*fi[9] + dy*fi[10] + dz*fi[11];
        float zz  = fi[9]*zjx + fi[10]*zjy + fi[11]*zjz;
        float ddz = (dx*zjx + dy*zjy + dz*zjz) / dist;
        float zdd = (fi[9]*dx + fi[10]*dy + fi[11]*dz) / dist;
        float seqi = (float)seq[b*LSEQ + l];
        float seqj = (float)seq[b*LSEQ + j];
        float idist = fminf(fabsf(seqj - seqi), 8.0f);
        // coords1 order: [eucl0,eucl1,eucl2, idist, zz, deltadotz, zdotdelta]
        co_s[warp][k][0] = e0;  co_s[warp][k][1] = e1;  co_s[warp][k][2] = e2;
        co_s[warp][k][3] = idist; co_s[warp][k][4] = zz;
        co_s[warp][k][5] = ddz; co_s[warp][k][6] = zdd;
    } else {
        int k = lane - K1N;
        int j = g_idx2[row*K2N + k];
        const float* ap = attr + ((size_t)b*LSEQ + j) * HIN;
        #pragma unroll
        for (int h = 0; h < HIN; h++) attr_s[warp][k][h] = ap[h];
    }
    __syncwarp();

    int g = lane;                       // gaussian group
    float cen[7], pr[49];
    #pragma unroll
    for (int d = 0; d < 7; d++)  cen[d] = gk1_centers[d*NG + g];
    #pragma unroll
    for (int i = 0; i < 49; i++) pr[i]  = gk1_prec[i*NG + g];   // [(d*7+c)*NG+g]

    float acc[HIN];
    #pragma unroll
    for (int h = 0; h < HIN; h++) acc[h] = 0.f;

    for (int k = 0; k < K1N; k++) {
        float diff[7];
        #pragma unroll
        for (int d = 0; d < 7; d++) diff[d] = co_s[warp][k][d] - cen[d];
        float s = 0.f;
        #pragma unroll
        for (int c = 0; c < 7; c++) {
            float y = 0.f;
            #pragma unroll
            for (int d = 0; d < 7; d++) y += diff[d] * pr[d*7 + c];
            s += y*y;
        }
        float gv = expf(-0.5f * s);
        #pragma unroll
        for (int h = 0; h < HIN; h++) acc[h] += gv * attr_s[warp][k][h];
    }
    float* mp = &g_M[(size_t)row*KDIM + g*HIN];
    #pragma unroll
    for (int h = 0; h < HIN; h++) mp[h] = acc[h];
}

// ---------------- kernel 3: GEMM (16384x640 @ 640x128) + fused MLP heads -----
__global__ void __launch_bounds__(256) gemm_epi_kernel(
    const float* __restrict__ opk,  const float* __restrict__ opb,
    const float* __restrict__ embW, const float* __restrict__ embb,
    const float* __restrict__ betaW, const float* __restrict__ betab,
    const float* __restrict__ sattW, const float* __restrict__ sattb,
    const float* __restrict__ cattW, const float* __restrict__ cattb,
    const float* __restrict__ nodefW, const float* __restrict__ nodefb)
{
    // union: mainloop As[16][68]+Bs[16][132] = 3200 floats; epilogue filt[64][132]+emb[64][33] = 10560 floats
    __shared__ __align__(16) float smem[10560];
    float* As     = smem;             // [16][68]
    float* Bs     = smem + 16*68;     // [16][132]
    float* filt_s = smem;             // [64][132]
    float* emb_s  = smem + 64*132;    // [64][33]

    int t  = threadIdx.x;
    int ty = t >> 4, tx = t & 15;
    int row0 = blockIdx.x * 64;

    float acc[4][8];
    #pragma unroll
    for (int i = 0; i < 4; i++)
        #pragma unroll
        for (int j = 0; j < 8; j++) acc[i][j] = 0.f;

    int ar = t >> 2, ako = (t & 3) << 2;     // A tile: 64 rows x 16 k, float4/thread
    int bk = t >> 5, bn  = (t & 31) << 2;    // B tile: 16 k x 128 n, 2 float4/thread

    for (int k0 = 0; k0 < KDIM; k0 += 16) {
        float4 av = *(const float4*)(&g_M[(size_t)(row0+ar)*KDIM + k0 + ako]);
        float4 b0 = *(const float4*)(&opk[(size_t)(k0+bk  )*DM + bn]);
        float4 b1 = *(const float4*)(&opk[(size_t)(k0+bk+8)*DM + bn]);
        As[(ako+0)*68+ar]=av.x; As[(ako+1)*68+ar]=av.y;
        As[(ako+2)*68+ar]=av.z; As[(ako+3)*68+ar]=av.w;
        *(float4*)(&Bs[ bk   *132+bn]) = b0;
        *(float4*)(&Bs[(bk+8)*132+bn]) = b1;
        __syncthreads();
        #pragma unroll
        for (int kk = 0; kk < 16; kk++) {
            float4 a = *(const float4*)(&As[kk*68 + ty*4]);
            float4 p = *(const float4*)(&Bs[kk*132 + tx*8]);
            float4 q = *(const float4*)(&Bs[kk*132 + tx*8 + 4]);
            float aa[4] = {a.x,a.y,a.z,a.w};
            float bb[8] = {p.x,p.y,p.z,p.w,q.x,q.y,q.z,q.w};
            #pragma unroll
            for (int i = 0; i < 4; i++)
                #pragma unroll
                for (int j = 0; j < 8; j++) acc[i][j] += aa[i]*bb[j];
        }
        __syncthreads();
    }

    // epilogue: relu(filt) into shared (As/Bs dead; last sync above protects union)
    #pragma unroll
    for (int i = 0; i < 4; i++)
        #pragma unroll
        for (int j = 0; j < 8; j++) {
            int col = tx*8 + j;
            filt_s[(ty*4+i)*132 + col] = fmaxf(acc[i][j] + opb[col], 0.f);
        }
    __syncthreads();

    // emb = relu(filt @ embW + embb): thread t -> row t>>2, cols (t&3)*8 .. +7
    {
        int r  = t >> 2;
        int jb = (t & 3) * 8;
        #pragma unroll
        for (int q = 0; q < 8; q++) {
            int j = jb + q;
            float s = embb[j];
            #pragma unroll 8
            for (int c = 0; c < DM; c++) s += filt_s[r*132 + c] * embW[c*DH + j];
            emb_s[r*33 + j] = fmaxf(s, 0.f);
        }
    }
    __syncthreads();

    if (t < 64) {
        int ri = row0 + t;
        float e[DH];
        #pragma unroll
        for (int j = 0; j < DH; j++) e[j] = emb_s[t*33 + j];
        float vb = betab[0], vs = sattb[0], vc = cattb[0];
        float n0 = nodefb[0], n1 = nodefb[1];
        #pragma unroll
        for (int j = 0; j < DH; j++) {
            vb += e[j]*betaW[j];
            vs += e[j]*sattW[j];
            vc += e[j]*cattW[j];
            n0 += e[j]*nodefW[j*2+0];
            n1 += e[j]*nodefW[j*2+1];
        }
        g_beta[ri]      = fmaxf(vb, 0.f);
        g_satt[ri]      = fmaxf(vs, 0.f);
        g_catt[ri]      = fmaxf(vc, 0.f);
        g_nodef[ri*2+0] = fmaxf(n0, 0.f);
        g_nodef[ri*2+1] = fmaxf(n1, 0.f);
    }
}

// ---------------- kernel 4: stage-2 gaussians + softmax attention -----------
__global__ void __launch_bounds__(256) stage2_kernel(
    const float* __restrict__ frame, const int* __restrict__ seq,
    const float* __restrict__ gk2_centers, const float* __restrict__ gk2_prec,
    const float* __restrict__ emb2W, const float* __restrict__ emb2b,
    float* __restrict__ out)
{
    __shared__ float c2s[5*NG];
    __shared__ float p2s[25*NG];
    __shared__ float w2s[NG];
    for (int i = threadIdx.x; i < 5*NG;  i += blockDim.x) c2s[i] = gk2_centers[i];
    for (int i = threadIdx.x; i < 25*NG; i += blockDim.x) p2s[i] = gk2_prec[i];
    if (threadIdx.x < NG) w2s[threadIdx.x] = emb2W[threadIdx.x];
    __syncthreads();

    int warp = threadIdx.x >> 5, lane = threadIdx.x & 31;
    int row  = blockIdx.x * 8 + warp;
    int b = row >> 11, l = row & (LSEQ-1);
    const float* fb = frame + (size_t)b * LSEQ * 12;

    int j  = g_idx2[row*K2N + lane];
    int jg = b*LSEQ + j;

    float cix = fb[l*12+0], ciy = fb[l*12+1], ciz = fb[l*12+2];
    float zix = fb[l*12+9], ziy = fb[l*12+10], ziz = fb[l*12+11];
    float cjx = fb[j*12+0], cjy = fb[j*12+1], cjz = fb[j*12+2];
    float zjx = fb[j*12+9], zjy = fb[j*12+10], zjz = fb[j*12+11];
    float dx = cjx-cix, dy = cjy-ciy, dz = cjz-ciz;
    float dist = sqrtf(dx*dx + dy*dy + dz*dz + 1e-12f);
    float zz  = zix*zjx + ziy*zjy + ziz*zjz;
    float ddz = (dx*zjx + dy*zjy + dz*zjz) / dist;
    float zdd = (zix*dx + ziy*dy + ziz*dz) / dist;
    float seqi = (float)seq[b*LSEQ+l];
    float seqj = (float)seq[jg];
    float idist = fminf(fabsf(seqj-seqi), 8.0f);
    // coords2 order: [dist, zz, deltadotz, zdotdelta, idist]
    float x[5] = {dist, zz, ddz, zdd, idist};

    float gw = emb2b[0];
    for (int n = 0; n < NG; n++) {
        float diff[5];
        #pragma unroll
        for (int d = 0; d < 5; d++) diff[d] = x[d] - c2s[d*NG+n];
        float s = 0.f;
        #pragma unroll
        for (int c = 0; c < 5; c++) {
            float y = 0.f;
            #pragma unroll
            for (int d = 0; d < 5; d++) y += diff[d]*p2s[(d*5+c)*NG+n];
            s += y*y;
        }
        gw += expf(-0.5f*s) * w2s[n];
    }
    gw = fmaxf(gw, 0.f);

    float e = (lane == 0) ? g_satt[row] : g_catt[jg];
    float logit = g_beta[row] * e;
    float mx = logit;
    #pragma unroll
    for (int off = 16; off > 0; off >>= 1)
        mx = fmaxf(mx, __shfl_xor_sync(0xffffffffu, mx, off));
    float w = gw * expf(logit - mx);
    float sw = w;
    #pragma unroll
    for (int off = 16; off > 0; off >>= 1)
        sw += __shfl_xor_sync(0xffffffffu, sw, off);
    float a = w / (sw + 1e-6f);
    float o0 = a * g_nodef[jg*2+0];
    float o1 = a * g_nodef[jg*2+1];
    #pragma unroll
    for (int off = 16; off > 0; off >>= 1) {
        o0 += __shfl_xor_sync(0xffffffffu, o0, off);
        o1 += __shfl_xor_sync(0xffffffffu, o1, off);
    }
    if (lane == 0) { out[row*2+0] = o0; out[row*2+1] = o1; }
}

// ---------------- launcher --------------------------------------------------
extern "C" void kernel_launch(void* const* d_in, const int* in_sizes, int n_in,
                              void* d_out, int out_size)
{
    const float* attr        = (const float*)d_in[0];
    const float* frame       = (const float*)d_in[1];
    const int*   seq         = (const int*)  d_in[2];
    const float* gk1_centers = (const float*)d_in[3];
    const float* gk1_prec    = (const float*)d_in[4];
    const float* opk         = (const float*)d_in[5];
    const float* opb         = (const float*)d_in[6];
    const float* embW        = (const float*)d_in[7];
    const float* embb        = (const float*)d_in[8];
    const float* betaW       = (const float*)d_in[9];
    const float* betab       = (const float*)d_in[10];
    const float* sattW       = (const float*)d_in[11];
    const float* sattb       = (const float*)d_in[12];
    const float* cattW       = (const float*)d_in[13];
    const float* cattb       = (const float*)d_in[14];
    const float* nodefW      = (const float*)d_in[15];
    const float* nodefb      = (const float*)d_in[16];
    const float* gk2_centers = (const float*)d_in[17];
    const float* gk2_prec    = (const float*)d_in[18];
    const float* emb2W       = (const float*)d_in[19];
    const float* emb2b       = (const float*)d_in[20];
    float* out = (float*)d_out;

    knn_kernel<<<NROWS/4, 128>>>(frame);
    stage1_kernel<<<NROWS/8, 256>>>(frame, attr, seq, gk1_centers, gk1_prec);
    gemm_epi_kernel<<<NROWS/64, 256>>>(opk, opb, embW, embb, betaW, betab,
                                       sattW, sattb, cattW, cattb, nodefW, nodefb);
    stage2_kernel<<<NROWS/8, 256>>>(frame, seq, gk2_centers, gk2_prec,
                                    emb2W, emb2b, out);
}

// round 2
// speedup vs baseline: 2.4687x; 2.4687x over previous
#include <cuda_runtime.h>
#include <math_constants.h>
#include <cstdint>

#define LSEQ 2048
#define BATCH 8
#define NROWS (BATCH*LSEQ)
#define K2N 32
#define K1N 16
#define NG 32
#define HIN 20
#define DM 128
#define DH 32
#define KDIM 640   // NG*HIN

// ---------------- device scratch (static, no allocation) ----------------
__device__ float4 g_cpack[NROWS];
__device__ int   g_idx2[NROWS*K2N];
__device__ float g_M[(size_t)NROWS*KDIM];     // layout: [row][h*32+g]
__device__ float g_satt[NROWS];
__device__ float g_catt[NROWS];
__device__ float g_beta[NROWS];
__device__ float g_nodef[NROWS*2];

// ---------------- kernel 0: pack coords + squared norm ----------------
__global__ void pack_kernel(const float* __restrict__ frame)
{
    int i = blockIdx.x * 256 + threadIdx.x;
    const float* f = frame + (size_t)i * 12;
    float x = f[0], y = f[1], z = f[2];
    g_cpack[i] = make_float4(x, y, z, x*x + y*y + z*z);
}

// ---------------- kernel 1: 32-NN per row, top-4 register cache ----------
__global__ void __launch_bounds__(128) knn_kernel()
{
    __shared__ float d2s[4][LSEQ];
    int warp = threadIdx.x >> 5, lane = threadIdx.x & 31;
    int row  = blockIdx.x * 4 + warp;
    int b = row >> 11, l = row & (LSEQ-1);
    const float4* cb = g_cpack + (size_t)b * LSEQ;
    float4 ci = cb[l];
    float* dw = d2s[warp];

    float v0 = CUDART_INF_F, v1 = CUDART_INF_F, v2 = CUDART_INF_F, v3 = CUDART_INF_F;
    int   p0 = 0x7fffffff,  p1 = 0x7fffffff,  p2 = 0x7fffffff,  p3 = 0x7fffffff;

    #pragma unroll 4
    for (int t = 0; t < LSEQ/32; t++) {
        int m = (t << 5) + lane;
        float4 cm = cb[m];
        float d = ci.w + cm.w - 2.0f*(ci.x*cm.x + ci.y*cm.y + ci.z*cm.z);
        dw[m] = d;
        if (d < v3) {
            if (d < v1) {
                v3 = v2; p3 = p2; v2 = v1; p2 = p1;
                if (d < v0) { v1 = v0; p1 = p0; v0 = d; p0 = m; }
                else        { v1 = d;  p1 = m; }
            } else {
                if (d < v2) { v3 = v2; p3 = p2; v2 = d; p2 = m; }
                else        { v3 = d;  p3 = m; }
            }
        }
    }
    __syncwarp();

    int myidx = 0;
    for (int s = 0; s < K2N; s++) {
        float v = v0; int p = p0;
        #pragma unroll
        for (int off = 16; off > 0; off >>= 1) {
            float ov = __shfl_down_sync(0xffffffffu, v, off);
            int   op = __shfl_down_sync(0xffffffffu, p, off);
            if (ov < v || (ov == v && op < p)) { v = ov; p = op; }
        }
        p = __shfl_sync(0xffffffffu, p, 0);
        if (lane == s) myidx = p;
        if (p0 == p) {                  // unique owner lane
            dw[p] = CUDART_INF_F;
            v0 = v1; p0 = p1; v1 = v2; p1 = p2; v2 = v3; p2 = p3;
            v3 = CUDART_INF_F; p3 = 0x7fffffff;
            if (v0 == CUDART_INF_F) {   // rare: refill top-4 from smem
                v0 = v1 = v2 = v3 = CUDART_INF_F;
                p0 = p1 = p2 = p3 = 0x7fffffff;
                for (int t = 0; t < LSEQ/32; t++) {
                    int m = (t << 5) + lane;
                    float d = dw[m];
                    if (d < v3) {
                        if (d < v1) {
                            v3 = v2; p3 = p2; v2 = v1; p2 = p1;
                            if (d < v0) { v1 = v0; p1 = p0; v0 = d; p0 = m; }
                            else        { v1 = d;  p1 = m; }
                        } else {
                            if (d < v2) { v3 = v2; p3 = p2; v2 = d; p2 = m; }
                            else        { v3 = d;  p3 = m; }
                        }
                    }
                }
            }
        }
        __syncwarp();
    }
    g_idx2[row*K2N + lane] = myidx;
}

// ---------------- kernel 2: coords1 + gaussians1 + outer product M ----------
__global__ void __launch_bounds__(256) stage1_kernel(
    const float* __restrict__ frame, const float* __restrict__ attr,
    const int* __restrict__ seq,
    const float* __restrict__ gk1_centers, const float* __restrict__ gk1_prec)
{
    __shared__ __align__(8) float attr_s[8][K1N][HIN];
    __shared__ float co_s[8][K1N][7];
    int warp = threadIdx.x >> 5, lane = threadIdx.x & 31;
    int row  = blockIdx.x * 8 + warp;
    int b = row >> 11, l = row & (LSEQ-1);
    const float* fb = frame + (size_t)b * LSEQ * 12;

    if (lane < K1N) {
        int k = lane;
        int j = g_idx2[row*K2N + k];
        float fi[12];
        #pragma unroll
        for (int d = 0; d < 12; d++) fi[d] = fb[l*12+d];
        float cjx = fb[j*12+0], cjy = fb[j*12+1], cjz = fb[j*12+2];
        float zjx = fb[j*12+9], zjy = fb[j*12+10], zjz = fb[j*12+11];
        float dx = cjx - fi[0], dy = cjy - fi[1], dz = cjz - fi[2];
        float dist = sqrtf(dx*dx + dy*dy + dz*dz + 1e-12f);
        float e0 = dx*fi[3] + dy*fi[4] + dz*fi[5];
        float e1 = dx*fi[6] + dy*fi[7] + dz*fi[8];
        float e2 = dx*fi[9] + dy*fi[10] + dz*fi[11];
        float zz  = fi[9]*zjx + fi[10]*zjy + fi[11]*zjz;
        float ddz = (dx*zjx + dy*zjy + dz*zjz) / dist;
        float zdd = (fi[9]*dx + fi[10]*dy + fi[11]*dz) / dist;
        float seqi = (float)seq[b*LSEQ + l];
        float seqj = (float)seq[b*LSEQ + j];
        float idist = fminf(fabsf(seqj - seqi), 8.0f);
        co_s[warp][k][0] = e0;  co_s[warp][k][1] = e1;  co_s[warp][k][2] = e2;
        co_s[warp][k][3] = idist; co_s[warp][k][4] = zz;
        co_s[warp][k][5] = ddz; co_s[warp][k][6] = zdd;
    } else {
        int k = lane - K1N;
        int j = g_idx2[row*K2N + k];
        const float2* ap = (const float2*)(attr + ((size_t)b*LSEQ + j) * HIN);
        float2* dst = (float2*)&attr_s[warp][k][0];
        #pragma unroll
        for (int h = 0; h < HIN/2; h++) dst[h] = ap[h];
    }
    __syncwarp();

    int g = lane;                       // gaussian group
    float cen[7], pr[49];
    #pragma unroll
    for (int d = 0; d < 7; d++)  cen[d] = gk1_centers[d*NG + g];
    #pragma unroll
    for (int i = 0; i < 49; i++) pr[i]  = gk1_prec[i*NG + g];

    float acc[HIN];
    #pragma unroll
    for (int h = 0; h < HIN; h++) acc[h] = 0.f;

    for (int k = 0; k < K1N; k++) {
        float diff[7];
        #pragma unroll
        for (int d = 0; d < 7; d++) diff[d] = co_s[warp][k][d] - cen[d];
        float s = 0.f;
        #pragma unroll
        for (int c = 0; c < 7; c++) {
            float y = 0.f;
            #pragma unroll
            for (int d = 0; d < 7; d++) y += diff[d] * pr[d*7 + c];
            s += y*y;
        }
        float gv = __expf(-0.5f * s);
        const float2* av = (const float2*)&attr_s[warp][k][0];
        #pragma unroll
        for (int h = 0; h < HIN/2; h++) {
            float2 a = av[h];
            acc[2*h+0] += gv * a.x;
            acc[2*h+1] += gv * a.y;
        }
    }
    // layout: g_M[row][h*32+g]  -> coalesced across lanes per h
    float* mp = &g_M[(size_t)row*KDIM + g];
    #pragma unroll
    for (int h = 0; h < HIN; h++) mp[h*NG] = acc[h];
}

// ---------------- kernel 3: 128x128x16 double-buffered GEMM + fused heads ---
// dynamic smem layout (floats):
//  [0..4223]      As0(16x132) Bs0(16x132)     -- union with filt_s/emb_s
//  [4224..8447]   As1 Bs1
//  filt_s = [0..16895] (128x132), emb_s = [16896..21119] (128x33)
//  embW_s = [21120..25215] (128x32)
#define GE_SMEM_FLOATS 25216
__global__ void __launch_bounds__(256) gemm_epi_kernel(
    const float* __restrict__ opk,  const float* __restrict__ opb,
    const float* __restrict__ embW, const float* __restrict__ embb,
    const float* __restrict__ betaW, const float* __restrict__ betab,
    const float* __restrict__ sattW, const float* __restrict__ sattb,
    const float* __restrict__ cattW, const float* __restrict__ cattb,
    const float* __restrict__ nodefW, const float* __restrict__ nodefb)
{
    extern __shared__ __align__(16) float sm[];
    float* embW_s = sm + 21120;

    int t  = threadIdx.x;
    int ty = t >> 4, tx = t & 15;
    int row0 = blockIdx.x * 128;

    for (int i = t; i < DM*DH; i += 256) embW_s[i] = embW[i];

    // A: thread loads row am, k-offsets ac0..ac0+3 and ac0+4..+7
    int am  = t >> 1;
    int ac0 = (t & 1) * 8;
    const float* Ap = g_M + (size_t)(row0 + am) * KDIM;
    // B: thread loads smem row bk, cols bn0..bn0+7
    int bk  = t >> 4;
    int bn0 = ((2*t) & 31) * 4;

    float4 aR0, aR1, bR0, bR1;
    aR0 = *(const float4*)(Ap + ac0);
    aR1 = *(const float4*)(Ap + ac0 + 4);
    {
        int k = bk;
        int sr = (k & 31)*HIN + (k >> 5);   // remap: k=h*32+g -> opk row g*20+h
        bR0 = *(const float4*)(opk + sr*DM + bn0);
        bR1 = *(const float4*)(opk + sr*DM + bn0 + 4);
    }
    {
        float* As = sm;  float* Bs = sm + 2112;
        As[(ac0+0)*132+am]=aR0.x; As[(ac0+1)*132+am]=aR0.y;
        As[(ac0+2)*132+am]=aR0.z; As[(ac0+3)*132+am]=aR0.w;
        As[(ac0+4)*132+am]=aR1.x; As[(ac0+5)*132+am]=aR1.y;
        As[(ac0+6)*132+am]=aR1.z; As[(ac0+7)*132+am]=aR1.w;
        *(float4*)&Bs[bk*132+bn0]   = bR0;
        *(float4*)&Bs[bk*132+bn0+4] = bR1;
    }
    __syncthreads();

    float acc[8][8];
    #pragma unroll
    for (int i = 0; i < 8; i++)
        #pragma unroll
        for (int j = 0; j < 8; j++) acc[i][j] = 0.f;

    for (int it = 0; it < KDIM/16; it++) {
        float* Asb = sm + (it & 1) * 4224;
        float* Bsb = Asb + 2112;
        if (it < KDIM/16 - 1) {
            int k0 = (it+1) * 16;
            aR0 = *(const float4*)(Ap + k0 + ac0);
            aR1 = *(const float4*)(Ap + k0 + ac0 + 4);
            int k = k0 + bk;
            int sr = (k & 31)*HIN + (k >> 5);
            bR0 = *(const float4*)(opk + sr*DM + bn0);
            bR1 = *(const float4*)(opk + sr*DM + bn0 + 4);
        }
        #pragma unroll
        for (int kk = 0; kk < 16; kk++) {
            float4 a0 = *(const float4*)&Asb[kk*132 + ty*8];
            float4 a1 = *(const float4*)&Asb[kk*132 + ty*8 + 4];
            float4 b0 = *(const float4*)&Bsb[kk*132 + tx*8];
            float4 b1 = *(const float4*)&Bsb[kk*132 + tx*8 + 4];
            float av[8] = {a0.x,a0.y,a0.z,a0.w,a1.x,a1.y,a1.z,a1.w};
            float bv[8] = {b0.x,b0.y,b0.z,b0.w,b1.x,b1.y,b1.z,b1.w};
            #pragma unroll
            for (int i = 0; i < 8; i++)
                #pragma unroll
                for (int j = 0; j < 8; j++) acc[i][j] += av[i]*bv[j];
        }
        if (it < KDIM/16 - 1) {
            float* Asn = sm + ((it+1) & 1) * 4224;
            float* Bsn = Asn + 2112;
            Asn[(ac0+0)*132+am]=aR0.x; Asn[(ac0+1)*132+am]=aR0.y;
            Asn[(ac0+2)*132+am]=aR0.z; Asn[(ac0+3)*132+am]=aR0.w;
            Asn[(ac0+4)*132+am]=aR1.x; Asn[(ac0+5)*132+am]=aR1.y;
            Asn[(ac0+6)*132+am]=aR1.z; Asn[(ac0+7)*132+am]=aR1.w;
            *(float4*)&Bsn[bk*132+bn0]   = bR0;
            *(float4*)&Bsn[bk*132+bn0+4] = bR1;
        }
        __syncthreads();
    }

    // epilogue: relu(filt) into shared union
    float* filt_s = sm;
    #pragma unroll
    for (int i = 0; i < 8; i++)
        #pragma unroll
        for (int j = 0; j < 8; j++) {
            int col = tx*8 + j;
            filt_s[(ty*8+i)*132 + col] = fmaxf(acc[i][j] + opb[col], 0.f);
        }
    __syncthreads();

    // emb = relu(filt @ embW + embb)
    float* emb_s = sm + 16896;
    {
        int r  = t >> 1;
        int jb = (t & 1) * 16;
        float s[16];
        #pragma unroll
        for (int q = 0; q < 16; q++) s[q] = embb[jb+q];
        #pragma unroll 8
        for (int c = 0; c < DM; c++) {
            float f = filt_s[r*132 + c];
            float4 w0 = *(const float4*)&embW_s[c*DH + jb];
            float4 w1 = *(const float4*)&embW_s[c*DH + jb + 4];
            float4 w2 = *(const float4*)&embW_s[c*DH + jb + 8];
            float4 w3 = *(const float4*)&embW_s[c*DH + jb + 12];
            s[0]+=f*w0.x;  s[1]+=f*w0.y;  s[2]+=f*w0.z;  s[3]+=f*w0.w;
            s[4]+=f*w1.x;  s[5]+=f*w1.y;  s[6]+=f*w1.z;  s[7]+=f*w1.w;
            s[8]+=f*w2.x;  s[9]+=f*w2.y;  s[10]+=f*w2.z; s[11]+=f*w2.w;
            s[12]+=f*w3.x; s[13]+=f*w3.y; s[14]+=f*w3.z; s[15]+=f*w3.w;
        }
        #pragma unroll
        for (int q = 0; q < 16; q++) emb_s[r*33 + jb + q] = fmaxf(s[q], 0.f);
    }
    __syncthreads();

    if (t < 128) {
        int ri = row0 + t;
        float vb = betab[0], vs = sattb[0], vc = cattb[0];
        float n0 = nodefb[0], n1 = nodefb[1];
        #pragma unroll
        for (int j = 0; j < DH; j++) {
            float e = emb_s[t*33 + j];
            vb += e*betaW[j];
            vs += e*sattW[j];
            vc += e*cattW[j];
            n0 += e*nodefW[j*2+0];
            n1 += e*nodefW[j*2+1];
        }
        g_beta[ri]      = fmaxf(vb, 0.f);
        g_satt[ri]      = fmaxf(vs, 0.f);
        g_catt[ri]      = fmaxf(vc, 0.f);
        g_nodef[ri*2+0] = fmaxf(n0, 0.f);
        g_nodef[ri*2+1] = fmaxf(n1, 0.f);
    }
}

// ---------------- kernel 4: stage-2 gaussians (register coeffs) + softmax ---
__global__ void __launch_bounds__(256) stage2_kernel(
    const float* __restrict__ frame, const int* __restrict__ seq,
    const float* __restrict__ gk2_centers, const float* __restrict__ gk2_prec,
    const float* __restrict__ emb2W, const float* __restrict__ emb2b,
    float* __restrict__ out)
{
    int warp = threadIdx.x >> 5, lane = threadIdx.x & 31;
    int row  = blockIdx.x * 8 + warp;
    int b = row >> 11, l = row & (LSEQ-1);
    const float* fb = frame + (size_t)b * LSEQ * 12;

    int j  = g_idx2[row*K2N + lane];
    int jg = b*LSEQ + j;

    float cix = fb[l*12+0], ciy = fb[l*12+1], ciz = fb[l*12+2];
    float zix = fb[l*12+9], ziy = fb[l*12+10], ziz = fb[l*12+11];
    float cjx = fb[j*12+0], cjy = fb[j*12+1], cjz = fb[j*12+2];
    float zjx = fb[j*12+9], zjy = fb[j*12+10], zjz = fb[j*12+11];
    float dx = cjx-cix, dy = cjy-ciy, dz = cjz-ciz;
    float dist = sqrtf(dx*dx + dy*dy + dz*dz + 1e-12f);
    float zz  = zix*zjx + ziy*zjy + ziz*zjz;
    float ddz = (dx*zjx + dy*zjy + dz*zjz) / dist;
    float zdd = (zix*dx + ziy*dy + ziz*dz) / dist;
    float seqi = (float)seq[b*LSEQ+l];
    float seqj = (float)seq[jg];
    float idist = fminf(fabsf(seqj-seqi), 8.0f);
    float x0 = dist, x1 = zz, x2 = ddz, x3 = zdd, x4 = idist;

    // per-lane gaussian n = lane: coefficients in registers
    float cen[5], pr[25];
    #pragma unroll
    for (int d = 0; d < 5; d++)  cen[d] = gk2_centers[d*NG + lane];
    #pragma unroll
    for (int i = 0; i < 25; i++) pr[i]  = gk2_prec[i*NG + lane];
    float wn = emb2W[lane];

    float gw_mine = 0.f;
    #pragma unroll 4
    for (int k = 0; k < K2N; k++) {
        float y0 = __shfl_sync(0xffffffffu, x0, k);
        float y1 = __shfl_sync(0xffffffffu, x1, k);
        float y2 = __shfl_sync(0xffffffffu, x2, k);
        float y3 = __shfl_sync(0xffffffffu, x3, k);
        float y4 = __shfl_sync(0xffffffffu, x4, k);
        float d0 = y0-cen[0], d1 = y1-cen[1], d2 = y2-cen[2], d3 = y3-cen[3], d4 = y4-cen[4];
        float s = 0.f;
        #pragma unroll
        for (int c = 0; c < 5; c++) {
            float yv = d0*pr[0*5+c] + d1*pr[1*5+c] + d2*pr[2*5+c]
                     + d3*pr[3*5+c] + d4*pr[4*5+c];
            s += yv*yv;
        }
        float e = __expf(-0.5f*s) * wn;
        #pragma unroll
        for (int off = 16; off > 0; off >>= 1)
            e += __shfl_xor_sync(0xffffffffu, e, off);
        if (lane == k) gw_mine = e;
    }
    float gw = fmaxf(gw_mine + emb2b[0], 0.f);

    float e = (lane == 0) ? g_satt[row] : g_catt[jg];
    float logit = g_beta[row] * e;
    float mx = logit;
    #pragma unroll
    for (int off = 16; off > 0; off >>= 1)
        mx = fmaxf(mx, __shfl_xor_sync(0xffffffffu, mx, off));
    float w = gw * __expf(logit - mx);
    float sw = w;
    #pragma unroll
    for (int off = 16; off > 0; off >>= 1)
        sw += __shfl_xor_sync(0xffffffffu, sw, off);
    float a = w / (sw + 1e-6f);
    float o0 = a * g_nodef[jg*2+0];
    float o1 = a * g_nodef[jg*2+1];
    #pragma unroll
    for (int off = 16; off > 0; off >>= 1) {
        o0 += __shfl_xor_sync(0xffffffffu, o0, off);
        o1 += __shfl_xor_sync(0xffffffffu, o1, off);
    }
    if (lane == 0) { out[row*2+0] = o0; out[row*2+1] = o1; }
}

// ---------------- launcher --------------------------------------------------
extern "C" void kernel_launch(void* const* d_in, const int* in_sizes, int n_in,
                              void* d_out, int out_size)
{
    const float* attr        = (const float*)d_in[0];
    const float* frame       = (const float*)d_in[1];
    const int*   seq         = (const int*)  d_in[2];
    const float* gk1_centers = (const float*)d_in[3];
    const float* gk1_prec    = (const float*)d_in[4];
    const float* opk         = (const float*)d_in[5];
    const float* opb         = (const float*)d_in[6];
    const float* embW        = (const float*)d_in[7];
    const float* embb        = (const float*)d_in[8];
    const float* betaW       = (const float*)d_in[9];
    const float* betab       = (const float*)d_in[10];
    const float* sattW       = (const float*)d_in[11];
    const float* sattb       = (const float*)d_in[12];
    const float* cattW       = (const float*)d_in[13];
    const float* cattb       = (const float*)d_in[14];
    const float* nodefW      = (const float*)d_in[15];
    const float* nodefb      = (const float*)d_in[16];
    const float* gk2_centers = (const float*)d_in[17];
    const float* gk2_prec    = (const float*)d_in[18];
    const float* emb2W       = (const float*)d_in[19];
    const float* emb2b       = (const float*)d_in[20];
    float* out = (float*)d_out;

    cudaFuncSetAttribute(gemm_epi_kernel,
                         cudaFuncAttributeMaxDynamicSharedMemorySize,
                         GE_SMEM_FLOATS * 4);

    pack_kernel<<<NROWS/256, 256>>>(frame);
    knn_kernel<<<NROWS/4, 128>>>();
    stage1_kernel<<<NROWS/8, 256>>>(frame, attr, seq, gk1_centers, gk1_prec);
    gemm_epi_kernel<<<NROWS/128, 256, GE_SMEM_FLOATS*4>>>(
        opk, opb, embW, embb, betaW, betab,
        sattW, sattb, cattW, cattb, nodefW, nodefb);
    stage2_kernel<<<NROWS/8, 256>>>(frame, seq, gk2_centers, gk2_prec,
                                    emb2W, emb2b, out);
}